// round 7
// baseline (speedup 1.0000x reference)
#include <cuda_runtime.h>
#include <cuda_bf16.h>
#include <cstdint>

#define NTOK 4096
#define DIM  1024
#define HDIM 4096
#define NE   8
#define TK   32

__device__ int   g_counts[NE];
__device__ int   g_tlist[NE * NTOK];
__device__ float g_h[(size_t)NTOK * HDIM];   // relu(x@fc)^2 scratch, 64 MB

// ---------------- helpers ----------------
__device__ __forceinline__ uint32_t smem_u32(const void* p) {
    uint32_t a;
    asm("{ .reg .u64 t; cvta.to.shared.u64 t, %1; cvt.u32.u64 %0, t; }" : "=r"(a) : "l"(p));
    return a;
}
__device__ __forceinline__ void ldm_x4(uint32_t& r0, uint32_t& r1, uint32_t& r2, uint32_t& r3, uint32_t a) {
    asm volatile("ldmatrix.sync.aligned.m8n8.x4.shared.b16 {%0,%1,%2,%3}, [%4];"
                 : "=r"(r0), "=r"(r1), "=r"(r2), "=r"(r3) : "r"(a));
}
__device__ __forceinline__ void ldm_x2(uint32_t& r0, uint32_t& r1, uint32_t a) {
    asm volatile("ldmatrix.sync.aligned.m8n8.x2.shared.b16 {%0,%1}, [%2];"
                 : "=r"(r0), "=r"(r1) : "r"(a));
}
__device__ __forceinline__ void ldm_x2t(uint32_t& r0, uint32_t& r1, uint32_t a) {
    asm volatile("ldmatrix.sync.aligned.m8n8.x2.trans.shared.b16 {%0,%1}, [%2];"
                 : "=r"(r0), "=r"(r1) : "r"(a));
}
__device__ __forceinline__ void mma16816(float* d, const uint32_t* a, uint32_t b0, uint32_t b1) {
    asm volatile("mma.sync.aligned.m16n8k16.row.col.f32.bf16.bf16.f32 "
                 "{%0,%1,%2,%3},{%4,%5,%6,%7},{%8,%9},{%0,%1,%2,%3};"
                 : "+f"(d[0]), "+f"(d[1]), "+f"(d[2]), "+f"(d[3])
                 : "r"(a[0]), "r"(a[1]), "r"(a[2]), "r"(a[3]), "r"(b0), "r"(b1));
}
__device__ __forceinline__ void split2(float x, float y, uint32_t& hi, uint32_t& lo) {
    __nv_bfloat16 hx = __float2bfloat16_rn(x);
    __nv_bfloat16 hy = __float2bfloat16_rn(y);
    __nv_bfloat16 lx = __float2bfloat16_rn(x - __bfloat162float(hx));
    __nv_bfloat16 ly = __float2bfloat16_rn(y - __bfloat162float(hy));
    hi = ((uint32_t)__bfloat16_as_ushort(hy) << 16) | __bfloat16_as_ushort(hx);
    lo = ((uint32_t)__bfloat16_as_ushort(ly) << 16) | __bfloat16_as_ushort(lx);
}
#define CP16(dst, src) \
    asm volatile("cp.async.cg.shared.global [%0], [%1], 16;" :: "r"(dst), "l"(src) : "memory")
#define CP_COMMIT() asm volatile("cp.async.commit_group;" ::: "memory")
#define CP_WAIT1()  asm volatile("cp.async.wait_group 1;" ::: "memory")

// ---------------------------------------------------------------------------
__global__ void init_counts_kernel() {
    if (threadIdx.x < NE) g_counts[threadIdx.x] = 0;
}

__global__ void router_kernel(const float* __restrict__ x,
                              const float* __restrict__ rw) {
    int warp = (blockIdx.x * blockDim.x + threadIdx.x) >> 5;
    int lane = threadIdx.x & 31;
    if (warp >= NTOK) return;
    const float* xr = x + (size_t)warp * DIM;
    float best = -1e30f;
    int bestE = 0;
#pragma unroll
    for (int e = 0; e < NE; e++) {
        const float* wr = rw + e * DIM;
        float p = 0.f;
        for (int k = lane; k < DIM; k += 32) p += xr[k] * wr[k];
#pragma unroll
        for (int o = 16; o; o >>= 1) p += __shfl_xor_sync(0xffffffffu, p, o);
        if (p > best) { best = p; bestE = e; }   // strict > => first-max (jnp.argmax)
    }
    if (lane == 0) {
        int slot = atomicAdd(&g_counts[bestE], 1);
        g_tlist[bestE * NTOK + slot] = warp;
    }
}

// ---------------------------------------------------------------------------
// Gathered grouped GEMM: R3-proven bf16 3-product split core, with the raw
// fp32 operands delivered by a 3-stage cp.async staging pipeline.
// BTRANS=true : B src elem (k,n) at Bq[k*HDIM + n]  (GEMM1, fc)   -> smem [k][n], ldmatrix.trans
// BTRANS=false: B src elem (n,k) at Bq[n*HDIM + k]  (GEMM2, proj) -> smem [n][k]
template <int KTOT, bool RELU2, bool BTRANS>
__global__ __launch_bounds__(256, 1) void gemm_mma(
    const float* __restrict__ Abase, int astride,
    const float* __restrict__ Bbase,
    float* __restrict__ Obase, int ostride)
{
    constexpr int KT      = KTOT / TK;
    // fp32 staging: A 128 rows x (128B data + 16B pad); B: BTRANS 32 rows x (512B+16B) else like A
    constexpr int A_STG   = 128 * 144;
    constexpr int B_STG   = BTRANS ? 32 * 528 : 128 * 144;
    constexpr int STG     = A_STG + B_STG;
    // bf16 tiles (R3 format): A [m][k] 80B stride; B BTRANS [k][n] 272B stride else [n][k] 80B
    constexpr int ASZ     = 128 * 80;
    constexpr int BSZ     = BTRANS ? 32 * 272 : 128 * 80;
    constexpr int TILES   = 512 + 3 * STG;           // byte offset of bf16 tiles

    const int e = blockIdx.z;
    const int count = g_counts[e];
    const int m0 = blockIdx.y * 128;
    if (m0 >= count) return;
    const int n0 = blockIdx.x * 128;

    extern __shared__ char smem[];
    int* toks = (int*)smem;
    const int tid = threadIdx.x;
    if (tid < 128) {
        int mg = m0 + tid;
        toks[tid] = (mg < count) ? g_tlist[e * NTOK + mg] : -1;
    }
    __syncthreads();

    const uint32_t sb = smem_u32(smem);
    const float* Bq = Bbase + (size_t)e * DIM * HDIM;

    // ---- cp.async slot mappings (mirror R3's LDG slots) ----
    const float* asrc[4];
    uint32_t adst[4];
    bool avalid[4];
#pragma unroll
    for (int q = 0; q < 4; q++) {
        int idx = q * 256 + tid;
        int row = idx >> 3, ch = idx & 7;        // 128 rows x 8 chunks(16B)
        int tok = toks[row];
        avalid[q] = (tok >= 0);
        if (tok < 0) tok = toks[0];
        asrc[q] = Abase + (size_t)tok * astride + ch * 4;
        adst[q] = (uint32_t)(row * 144 + ch * 16);
    }
    const float* bsrc[4];
    uint32_t bdst[4];
#pragma unroll
    for (int q = 0; q < 4; q++) {
        int idx = q * 256 + tid;
        if (BTRANS) {
            int kk = idx >> 5, nc = idx & 31;    // 32 k-rows x 32 chunks
            bsrc[q] = Bq + (size_t)kk * HDIM + n0 + nc * 4;
            bdst[q] = (uint32_t)(kk * 528 + nc * 16);
        } else {
            int row = idx >> 3, ch = idx & 7;    // 128 n-rows x 8 chunks
            bsrc[q] = Bq + (size_t)(n0 + row) * HDIM + ch * 4;
            bdst[q] = (uint32_t)(row * 144 + ch * 16);
        }
    }
    auto ISSUE = [&](int kt) {
        uint32_t st = sb + 512 + (kt % 3) * STG;
        int k0 = kt * TK;
#pragma unroll
        for (int q = 0; q < 4; q++) CP16(st + adst[q], asrc[q] + k0);
#pragma unroll
        for (int q = 0; q < 4; q++) {
            if (BTRANS) CP16(st + A_STG + bdst[q], bsrc[q] + (size_t)k0 * HDIM);
            else        CP16(st + A_STG + bdst[q], bsrc[q] + k0);
        }
        CP_COMMIT();
    };

    // ---- FILL: staging fp32 -> split -> bf16 tiles (R3 STORE layout verbatim) ----
    char* tilesb = smem + TILES;
    auto FILL = [&](int kt) {
        char* stg = smem + 512 + (kt % 3) * STG;
#pragma unroll
        for (int it = 0; it < 4; it++) {          // A
            int idx = it * 256 + tid;
            int row = idx >> 3, c4 = idx & 7;
            float4 v = *(const float4*)(stg + row * 144 + c4 * 16);
            if (!avalid[it]) v = make_float4(0.f, 0.f, 0.f, 0.f);
            uint32_t h0, l0, h1, l1;
            split2(v.x, v.y, h0, l0);
            split2(v.z, v.w, h1, l1);
            int off = row * 80 + c4 * 8;
            *(uint2*)(tilesb + off)       = make_uint2(h0, h1);
            *(uint2*)(tilesb + ASZ + off) = make_uint2(l0, l1);
        }
        char* bstg = stg + A_STG;
        char* bbase = tilesb + 2 * ASZ;
#pragma unroll
        for (int it = 0; it < 4; it++) {          // B
            int idx = it * 256 + tid;
            float4 v;
            int off;
            if (BTRANS) {
                int kk = idx >> 5, n4 = idx & 31;
                v = *(const float4*)(bstg + kk * 528 + n4 * 16);
                off = kk * 272 + n4 * 8;
            } else {
                int row = idx >> 3, c4 = idx & 7;
                v = *(const float4*)(bstg + row * 144 + c4 * 16);
                off = row * 80 + c4 * 8;
            }
            uint32_t h0, l0, h1, l1;
            split2(v.x, v.y, h0, l0);
            split2(v.z, v.w, h1, l1);
            *(uint2*)(bbase + off)       = make_uint2(h0, h1);
            *(uint2*)(bbase + BSZ + off) = make_uint2(l0, l1);
        }
    };

    // ---- fragment addressing (R3 verbatim) ----
    const int lane = tid & 31, warp = tid >> 5;
    const int wm = (warp >> 2) * 64, wn = (warp & 3) * 32;
    uint32_t a_addr[4];
#pragma unroll
    for (int mi = 0; mi < 4; mi++)
        a_addr[mi] = (uint32_t)((wm + mi * 16 + (lane & 15)) * 80 + (lane >> 4) * 16);
    uint32_t b_addr[4];
#pragma unroll
    for (int j = 0; j < 4; j++) {
        if (BTRANS)
            b_addr[j] = (uint32_t)((lane & 15) * 272 + (wn + j * 8) * 2);
        else
            b_addr[j] = (uint32_t)((wn + j * 8 + (lane & 7)) * 80 + ((lane >> 3) & 1) * 16);
    }

    float acc[4][4][4];
#pragma unroll
    for (int i = 0; i < 4; i++)
#pragma unroll
        for (int j = 0; j < 4; j++)
#pragma unroll
            for (int c = 0; c < 4; c++) acc[i][j][c] = 0.f;

    const uint32_t ab = sb + TILES;
    const uint32_t bb = ab + 2 * ASZ;

    ISSUE(0);
    ISSUE(1);

    for (int kt = 0; kt < KT; kt++) {
        CP_WAIT1();
        __syncthreads();                 // staging kt complete, prev compute done
        if (kt + 2 < KT) ISSUE(kt + 2); else CP_COMMIT();
        FILL(kt);
        __syncthreads();                 // bf16 tiles ready

        // ---- COMPUTE (R3 verbatim) ----
#pragma unroll
        for (int sl = 0; sl < 2; sl++) {
            uint32_t ah[4][4], al[4][4], bh[4][2], bl[4][2];
#pragma unroll
            for (int mi = 0; mi < 4; mi++) {
                uint32_t ad = ab + a_addr[mi] + sl * 32;
                ldm_x4(ah[mi][0], ah[mi][1], ah[mi][2], ah[mi][3], ad);
                ldm_x4(al[mi][0], al[mi][1], al[mi][2], al[mi][3], ad + ASZ);
            }
#pragma unroll
            for (int j = 0; j < 4; j++) {
                uint32_t bd = bb + b_addr[j] + (BTRANS ? sl * (16 * 272) : sl * 32);
                if (BTRANS) {
                    ldm_x2t(bh[j][0], bh[j][1], bd);
                    ldm_x2t(bl[j][0], bl[j][1], bd + BSZ);
                } else {
                    ldm_x2(bh[j][0], bh[j][1], bd);
                    ldm_x2(bl[j][0], bl[j][1], bd + BSZ);
                }
            }
#pragma unroll
            for (int mi = 0; mi < 4; mi++)
#pragma unroll
                for (int j = 0; j < 4; j++) {
                    mma16816(acc[mi][j], ah[mi], bh[j][0], bh[j][1]);
                    mma16816(acc[mi][j], ah[mi], bl[j][0], bl[j][1]);
                    mma16816(acc[mi][j], al[mi], bh[j][0], bh[j][1]);
                }
        }
    }

    // ---- epilogue (R3 verbatim) ----
#pragma unroll
    for (int mi = 0; mi < 4; mi++) {
        int r0 = wm + mi * 16 + (lane >> 2);
        int r1 = r0 + 8;
        int t0 = toks[r0], t1 = toks[r1];
#pragma unroll
        for (int j = 0; j < 4; j++) {
            int col = n0 + wn + j * 8 + (lane & 3) * 2;
            float2 v0 = make_float2(acc[mi][j][0], acc[mi][j][1]);
            float2 v1 = make_float2(acc[mi][j][2], acc[mi][j][3]);
            if (RELU2) {
                v0.x = fmaxf(v0.x, 0.f); v0.x *= v0.x;
                v0.y = fmaxf(v0.y, 0.f); v0.y *= v0.y;
                v1.x = fmaxf(v1.x, 0.f); v1.x *= v1.x;
                v1.y = fmaxf(v1.y, 0.f); v1.y *= v1.y;
            }
            if (t0 >= 0) *(float2*)(Obase + (size_t)t0 * ostride + col) = v0;
            if (t1 >= 0) *(float2*)(Obase + (size_t)t1 * ostride + col) = v1;
        }
    }
}

// ---------------------------------------------------------------------------
#define SMEM1 (512 + 3 * (128 * 144 + 32 * 528) + (2 * 128 * 80 + 2 * 32 * 272))   // 144384
#define SMEM2 (512 + 3 * (128 * 144 + 128 * 144) + (2 * 128 * 80 + 2 * 128 * 80))  // 152064

extern "C" void kernel_launch(void* const* d_in, const int* in_sizes, int n_in,
                              void* d_out, int out_size) {
    const float* x    = (const float*)d_in[0];
    const float* rw   = (const float*)d_in[1];
    const float* fc   = (const float*)d_in[2];
    const float* proj = (const float*)d_in[3];
    float* out = (float*)d_out;

    cudaFuncSetAttribute(gemm_mma<DIM, true, true>,
                         cudaFuncAttributeMaxDynamicSharedMemorySize, SMEM1);
    cudaFuncSetAttribute(gemm_mma<HDIM, false, false>,
                         cudaFuncAttributeMaxDynamicSharedMemorySize, SMEM2);

    init_counts_kernel<<<1, 32>>>();
    router_kernel<<<(NTOK * 32) / 256, 256>>>(x, rw);

    dim3 g1(HDIM / 128, NTOK / 128, NE);   // 32 x 32 x 8, most blocks early-exit
    gemm_mma<DIM, true, true><<<g1, 256, SMEM1>>>(x, DIM, fc, g_h, HDIM);

    dim3 g2(DIM / 128, NTOK / 128, NE);    // 8 x 32 x 8
    gemm_mma<HDIM, false, false><<<g2, 256, SMEM2>>>(g_h, HDIM, proj, out, DIM);
}

// round 8
// speedup vs baseline: 1.7496x; 1.7496x over previous
#include <cuda_runtime.h>
#include <cuda_bf16.h>
#include <cstdint>

#define NTOK 4096
#define DIM  1024
#define HDIM 4096
#define NE   8
#define TK   16

__device__ int   g_counts[NE];
__device__ int   g_tlist[NE * NTOK];
__device__ float g_h[(size_t)NTOK * HDIM];   // relu(x@fc)^2 scratch, 64 MB

// ---------------- helpers ----------------
__device__ __forceinline__ uint32_t smem_u32(const void* p) {
    uint32_t a;
    asm("{ .reg .u64 t; cvta.to.shared.u64 t, %1; cvt.u32.u64 %0, t; }" : "=r"(a) : "l"(p));
    return a;
}
__device__ __forceinline__ void ldm_x4(uint32_t& r0, uint32_t& r1, uint32_t& r2, uint32_t& r3, uint32_t a) {
    asm volatile("ldmatrix.sync.aligned.m8n8.x4.shared.b16 {%0,%1,%2,%3}, [%4];"
                 : "=r"(r0), "=r"(r1), "=r"(r2), "=r"(r3) : "r"(a));
}
__device__ __forceinline__ void ldm_x2(uint32_t& r0, uint32_t& r1, uint32_t a) {
    asm volatile("ldmatrix.sync.aligned.m8n8.x2.shared.b16 {%0,%1}, [%2];"
                 : "=r"(r0), "=r"(r1) : "r"(a));
}
__device__ __forceinline__ void ldm_x2t(uint32_t& r0, uint32_t& r1, uint32_t a) {
    asm volatile("ldmatrix.sync.aligned.m8n8.x2.trans.shared.b16 {%0,%1}, [%2];"
                 : "=r"(r0), "=r"(r1) : "r"(a));
}
__device__ __forceinline__ void mma16816(float* d, const uint32_t* a, uint32_t b0, uint32_t b1) {
    asm volatile("mma.sync.aligned.m16n8k16.row.col.f32.bf16.bf16.f32 "
                 "{%0,%1,%2,%3},{%4,%5,%6,%7},{%8,%9},{%0,%1,%2,%3};"
                 : "+f"(d[0]), "+f"(d[1]), "+f"(d[2]), "+f"(d[3])
                 : "r"(a[0]), "r"(a[1]), "r"(a[2]), "r"(a[3]), "r"(b0), "r"(b1));
}
__device__ __forceinline__ void split2(float x, float y, uint32_t& hi, uint32_t& lo) {
    __nv_bfloat16 hx = __float2bfloat16_rn(x);
    __nv_bfloat16 hy = __float2bfloat16_rn(y);
    __nv_bfloat16 lx = __float2bfloat16_rn(x - __bfloat162float(hx));
    __nv_bfloat16 ly = __float2bfloat16_rn(y - __bfloat162float(hy));
    hi = ((uint32_t)__bfloat16_as_ushort(hy) << 16) | __bfloat16_as_ushort(hx);
    lo = ((uint32_t)__bfloat16_as_ushort(ly) << 16) | __bfloat16_as_ushort(lx);
}

// ---------------------------------------------------------------------------
__global__ void init_counts_kernel() {
    if (threadIdx.x < NE) g_counts[threadIdx.x] = 0;
}

__global__ void router_kernel(const float* __restrict__ x,
                              const float* __restrict__ rw) {
    int warp = (blockIdx.x * blockDim.x + threadIdx.x) >> 5;
    int lane = threadIdx.x & 31;
    if (warp >= NTOK) return;
    const float* xr = x + (size_t)warp * DIM;
    float best = -1e30f;
    int bestE = 0;
#pragma unroll
    for (int e = 0; e < NE; e++) {
        const float* wr = rw + e * DIM;
        float p = 0.f;
        for (int k = lane; k < DIM; k += 32) p += xr[k] * wr[k];
#pragma unroll
        for (int o = 16; o; o >>= 1) p += __shfl_xor_sync(0xffffffffu, p, o);
        if (p > best) { best = p; bestE = e; }   // strict > => first-max (jnp.argmax)
    }
    if (lane == 0) {
        int slot = atomicAdd(&g_counts[bestE], 1);
        g_tlist[bestE * NTOK + slot] = warp;
    }
}

// ---------------------------------------------------------------------------
// Gathered grouped GEMM, R3-proven bf16 3-product split numerics.
// 512 threads / 16 warps, warp tile 32x32, TK=16, double-buffered smem.
// BTRANS=true : B src elem (k,n) at Bq[k*HDIM + n]  (GEMM1, fc)   -> smem [k][n], ldmatrix.trans
// BTRANS=false: B src elem (n,k) at Bq[n*HDIM + k]  (GEMM2, proj) -> smem [n][k]
template <int KTOT, bool RELU2, bool BTRANS>
__global__ __launch_bounds__(512, 1) void gemm_mma(
    const float* __restrict__ Abase, int astride,
    const float* __restrict__ Bbase,
    float* __restrict__ Obase, int ostride)
{
    constexpr int KT  = KTOT / TK;
    constexpr int ASZ = 128 * 48;                    // bf16 [m][k] tile, 48B row stride
    constexpr int BSZ = BTRANS ? 16 * 272 : 128 * 48;
    constexpr int STAGE = 2 * ASZ + 2 * BSZ;         // Ahi, Alo, Bhi, Blo

    const int e = blockIdx.z;
    const int count = g_counts[e];
    const int m0 = blockIdx.y * 128;
    if (m0 >= count) return;
    const int n0 = blockIdx.x * 128;

    extern __shared__ char smem[];
    int* toks = (int*)smem;
    const int tid = threadIdx.x;
    if (tid < 128) {
        int mg = m0 + tid;
        toks[tid] = (mg < count) ? g_tlist[e * NTOK + mg] : -1;
    }
    __syncthreads();

    const uint32_t sb = smem_u32(smem) + 512;        // tile stages base
    const float* Bq = Bbase + (size_t)e * DIM * HDIM;

    // ---- global load mappings: one float4 per thread per operand per iter ----
    const int arow = tid >> 2;                        // 0..127
    const int akq  = (tid & 3) * 4;                   // 0,4,8,12
    const int atok = toks[arow];
    const float* aptr = (atok >= 0) ? (Abase + (size_t)atok * astride + akq) : nullptr;

    const float* bptr;
    int bkk = 0, bn4 = 0, brow = 0, bkq = 0;
    if (BTRANS) {
        bkk = tid >> 5;                               // 0..15 (k)
        bn4 = (tid & 31) * 4;                         // 0..124 (n)
        bptr = Bq + (size_t)bkk * HDIM + n0 + bn4;
    } else {
        brow = tid >> 2;                              // 0..127 (n)
        bkq  = (tid & 3) * 4;                         // 0,4,8,12 (k)
        bptr = Bq + (size_t)(n0 + brow) * HDIM + bkq;
    }

    float4 ra, rb;
    auto LOAD = [&](int k0) {
        ra = aptr ? *(const float4*)(aptr + k0) : make_float4(0.f, 0.f, 0.f, 0.f);
        if (BTRANS) rb = *(const float4*)(bptr + (size_t)k0 * HDIM);
        else        rb = *(const float4*)(bptr + k0);
    };
    auto STORE = [&](int s) {
        char* base = smem + 512 + s * STAGE;
        uint32_t h0, l0, h1, l1;
        split2(ra.x, ra.y, h0, l0);
        split2(ra.z, ra.w, h1, l1);
        int offa = arow * 48 + (tid & 3) * 8;
        *(uint2*)(base + offa)       = make_uint2(h0, h1);
        *(uint2*)(base + ASZ + offa) = make_uint2(l0, l1);

        char* bbase = base + 2 * ASZ;
        split2(rb.x, rb.y, h0, l0);
        split2(rb.z, rb.w, h1, l1);
        int offb = BTRANS ? (bkk * 272 + (tid & 31) * 8) : (brow * 48 + bkq * 2);
        *(uint2*)(bbase + offb)       = make_uint2(h0, h1);
        *(uint2*)(bbase + BSZ + offb) = make_uint2(l0, l1);
    };

    // ---- fragment addressing (R3 formulas, 48/272B strides, single k16 slice) ----
    const int lane = tid & 31, warp = tid >> 5;
    const int wm = (warp >> 2) * 32;                  // 0,32,64,96
    const int wn = (warp & 3) * 32;                   // 0,32,64,96
    uint32_t a_addr[2];
#pragma unroll
    for (int mi = 0; mi < 2; mi++)
        a_addr[mi] = (uint32_t)((wm + mi * 16 + (lane & 15)) * 48 + (lane >> 4) * 16);
    uint32_t b_addr[4];
#pragma unroll
    for (int j = 0; j < 4; j++) {
        if (BTRANS)
            b_addr[j] = (uint32_t)((lane & 15) * 272 + (wn + j * 8) * 2);
        else
            b_addr[j] = (uint32_t)((wn + j * 8 + (lane & 7)) * 48 + ((lane >> 3) & 1) * 16);
    }

    float acc[2][4][4];
#pragma unroll
    for (int i = 0; i < 2; i++)
#pragma unroll
        for (int j = 0; j < 4; j++)
#pragma unroll
            for (int c = 0; c < 4; c++) acc[i][j][c] = 0.f;

    auto COMPUTE = [&](int s) {
        uint32_t ab = sb + s * STAGE;
        uint32_t bb = ab + 2 * ASZ;
        uint32_t ah[2][4], al[2][4], bh[4][2], bl[4][2];
#pragma unroll
        for (int mi = 0; mi < 2; mi++) {
            uint32_t ad = ab + a_addr[mi];
            ldm_x4(ah[mi][0], ah[mi][1], ah[mi][2], ah[mi][3], ad);
            ldm_x4(al[mi][0], al[mi][1], al[mi][2], al[mi][3], ad + ASZ);
        }
#pragma unroll
        for (int j = 0; j < 4; j++) {
            uint32_t bd = bb + b_addr[j];
            if (BTRANS) {
                ldm_x2t(bh[j][0], bh[j][1], bd);
                ldm_x2t(bl[j][0], bl[j][1], bd + BSZ);
            } else {
                ldm_x2(bh[j][0], bh[j][1], bd);
                ldm_x2(bl[j][0], bl[j][1], bd + BSZ);
            }
        }
#pragma unroll
        for (int mi = 0; mi < 2; mi++)
#pragma unroll
            for (int j = 0; j < 4; j++) {
                mma16816(acc[mi][j], ah[mi], bh[j][0], bh[j][1]);
                mma16816(acc[mi][j], ah[mi], bl[j][0], bl[j][1]);
                mma16816(acc[mi][j], al[mi], bh[j][0], bh[j][1]);
            }
    };

    // ---- main loop (R3 structure) ----
    LOAD(0);
    STORE(0);
    __syncthreads();
    for (int kt = 0; kt < KT; kt++) {
        int s = kt & 1;
        if (kt + 1 < KT) LOAD((kt + 1) * TK);
        COMPUTE(s);
        if (kt + 1 < KT) {
            __syncthreads();
            STORE(s ^ 1);
            __syncthreads();
        }
    }

    // ---- epilogue (R3 verbatim, mi in 0..1) ----
#pragma unroll
    for (int mi = 0; mi < 2; mi++) {
        int r0 = wm + mi * 16 + (lane >> 2);
        int r1 = r0 + 8;
        int t0 = toks[r0], t1 = toks[r1];
#pragma unroll
        for (int j = 0; j < 4; j++) {
            int col = n0 + wn + j * 8 + (lane & 3) * 2;
            float2 v0 = make_float2(acc[mi][j][0], acc[mi][j][1]);
            float2 v1 = make_float2(acc[mi][j][2], acc[mi][j][3]);
            if (RELU2) {
                v0.x = fmaxf(v0.x, 0.f); v0.x *= v0.x;
                v0.y = fmaxf(v0.y, 0.f); v0.y *= v0.y;
                v1.x = fmaxf(v1.x, 0.f); v1.x *= v1.x;
                v1.y = fmaxf(v1.y, 0.f); v1.y *= v1.y;
            }
            if (t0 >= 0) *(float2*)(Obase + (size_t)t0 * ostride + col) = v0;
            if (t1 >= 0) *(float2*)(Obase + (size_t)t1 * ostride + col) = v1;
        }
    }
}

// ---------------------------------------------------------------------------
#define SMEM1 (512 + 2 * (2 * 128 * 48 + 2 * 16 * 272))    // 42496
#define SMEM2 (512 + 2 * (2 * 128 * 48 + 2 * 128 * 48))    // 49664

extern "C" void kernel_launch(void* const* d_in, const int* in_sizes, int n_in,
                              void* d_out, int out_size) {
    const float* x    = (const float*)d_in[0];
    const float* rw   = (const float*)d_in[1];
    const float* fc   = (const float*)d_in[2];
    const float* proj = (const float*)d_in[3];
    float* out = (float*)d_out;

    cudaFuncSetAttribute(gemm_mma<DIM, true, true>,
                         cudaFuncAttributeMaxDynamicSharedMemorySize, SMEM1);
    cudaFuncSetAttribute(gemm_mma<HDIM, false, false>,
                         cudaFuncAttributeMaxDynamicSharedMemorySize, SMEM2);

    init_counts_kernel<<<1, 32>>>();
    router_kernel<<<(NTOK * 32) / 256, 256>>>(x, rw);

    dim3 g1(HDIM / 128, NTOK / 128, NE);   // 32 x 32 x 8, most blocks early-exit
    gemm_mma<DIM, true, true><<<g1, 512, SMEM1>>>(x, DIM, fc, g_h, HDIM);

    dim3 g2(DIM / 128, NTOK / 128, NE);    // 8 x 32 x 8
    gemm_mma<HDIM, false, false><<<g2, 512, SMEM2>>>(g_h, HDIM, proj, out, DIM);
}